// round 17
// baseline (speedup 1.0000x reference)
#include <cuda_runtime.h>
#include <cuda_fp16.h>
#include <stdint.h>

// Problem constants
#define BATCH 4096
#define FEAT  4096
#define MROWS 65536
#define EPS   1e-5f
#define QPRE  0.09017131f   // (1/sqrt(256)) * log2(e)

// ---------------- device scratch ----------------
#define RCHUNKS 128
__device__ float g_psum[RCHUNKS * FEAT];
__device__ float g_psumsq[RCHUNKS * FEAT];
__device__ float g_scale[FEAT];
__device__ float g_shift[FEAT];
__device__ uint32_t g_xnh[(size_t)MROWS * 128];  // BN(x) fp16x2, 32 MB
__device__ uint32_t g_wh[3 * 256 * 128];          // weights fp16x2 (WQ pre-scaled)

__device__ __forceinline__ uint32_t hpack(float y0, float y1) {
    uint32_t h;
    asm("cvt.rn.f16x2.f32 %0, %1, %2;" : "=r"(h) : "f"(y1), "f"(y0));
    return h;
}
__device__ __forceinline__ uint32_t hex2(uint32_t h) {
    uint32_t r;
    asm("ex2.approx.f16x2 %0, %1;" : "=r"(r) : "r"(h));
    return r;
}
__device__ __forceinline__ void cp16(uint32_t daddr, const void* src) {
    asm volatile("cp.async.cg.shared.global [%0], [%1], 16;"
                 :: "r"(daddr), "l"(src) : "memory");
}

#define MMA_FP16(c, a0, a1, a2, a3, b0, b1)                                \
    asm volatile(                                                          \
        "mma.sync.aligned.m16n8k16.row.col.f32.f16.f16.f32 "               \
        "{%0,%1,%2,%3}, {%4,%5,%6,%7}, {%8,%9}, {%0,%1,%2,%3};"            \
        : "+f"((c)[0]), "+f"((c)[1]), "+f"((c)[2]), "+f"((c)[3])           \
        : "r"(a0), "r"(a1), "r"(a2), "r"(a3), "r"(b0), "r"(b1))

// ---------------- BN pass 1 ----------------
__global__ void bn_pass1(const float* __restrict__ x) {
    int col = blockIdx.x * 256 + threadIdx.x;
    int r0  = blockIdx.y * (BATCH / RCHUNKS);
    float s = 0.f, ss = 0.f;
    #pragma unroll 4
    for (int r = 0; r < BATCH / RCHUNKS; r++) {
        float v = x[(size_t)(r0 + r) * FEAT + col];
        s += v; ss += v * v;
    }
    g_psum[blockIdx.y * FEAT + col]   = s;
    g_psumsq[blockIdx.y * FEAT + col] = ss;
}

// ---------------- BN pass 2 ----------------
__global__ void bn_pass2(const float* __restrict__ gamma,
                         const float* __restrict__ beta) {
    int col = blockIdx.x * blockDim.x + threadIdx.x;
    float s = 0.f, ss = 0.f;
    #pragma unroll
    for (int c = 0; c < RCHUNKS; c++) {
        s  += g_psum[c * FEAT + col];
        ss += g_psumsq[c * FEAT + col];
    }
    float mean = s * (1.f / BATCH);
    float var  = ss * (1.f / BATCH) - mean * mean;
    float rstd = rsqrtf(var + EPS);
    float a = rstd * gamma[col];
    g_scale[col] = a;
    g_shift[col] = beta[col] - mean * a;
}

// ---------------- xn -> fp16 (BN fused), 8 elems/thread ----------------
__global__ void xn_fp16(const float* __restrict__ x) {
    int i = blockIdx.x * 256 + threadIdx.x;
    size_t e = (size_t)i * 8;
    int col = (int)(e & 4095);
    float4 v0 = *(const float4*)(x + e);
    float4 v1 = *(const float4*)(x + e + 4);
    float4 sc0 = *(const float4*)(g_scale + col);
    float4 sc1 = *(const float4*)(g_scale + col + 4);
    float4 sh0 = *(const float4*)(g_shift + col);
    float4 sh1 = *(const float4*)(g_shift + col + 4);
    uint4 o;
    o.x = hpack(fmaf(v0.x, sc0.x, sh0.x), fmaf(v0.y, sc0.y, sh0.y));
    o.y = hpack(fmaf(v0.z, sc0.z, sh0.z), fmaf(v0.w, sc0.w, sh0.w));
    o.z = hpack(fmaf(v1.x, sc1.x, sh1.x), fmaf(v1.y, sc1.y, sh1.y));
    o.w = hpack(fmaf(v1.z, sc1.z, sh1.z), fmaf(v1.w, sc1.w, sh1.w));
    *(uint4*)(g_xnh + e / 2) = o;
}

// ---------------- W -> fp16 (WQ scaled by QPRE) ----------------
__global__ void w_fp16(const float* __restrict__ wq,
                       const float* __restrict__ wk,
                       const float* __restrict__ wv) {
    int i = blockIdx.x * 256 + threadIdx.x;
    int w = i >> 15;
    int idx = i & 32767;
    const float* src = (w == 0) ? wq : (w == 1) ? wk : wv;
    float2 v = ((const float2*)src)[idx];
    float s = (w == 0) ? QPRE : 1.f;
    g_wh[i] = hpack(v.x * s, v.y * s);
}

// ---------------- FUSED: QKV gemm + attention, 4 batches/CTA --------------
// Smem (u32): Qt[4][256][12] | Kt[4][256][12] | Vh[4][24][132] |
//             A[64][132] | W[2][256][20]
// W pitch = 20 u32 (multiple of 4 -> 16B-aligned cp.async destinations).
#define QT_OFF 0
#define KT_OFF 12288
#define VH_OFF 24576
#define A_OFF  37248
#define W_OFF  45696
#define WSTG   5120                        // 256*20 u32 per stage
#define SMEM_FUSED ((size_t)55936 * 4)     // 223744 bytes

__global__ void __launch_bounds__(256, 1) fused_qkv_attn(
    const float* __restrict__ x,
    const float* __restrict__ bq, const float* __restrict__ bk_,
    const float* __restrict__ bv, float* __restrict__ out)
{
    extern __shared__ uint32_t smq[];
    const int tid = threadIdx.x;
    const int lane = tid & 31, wid = tid >> 5;
    const int g4 = lane >> 2, l4 = lane & 3;
    const int m0 = blockIdx.x * 64;        // xn row base (4 batches x 16 p)

    uint32_t sbase = (uint32_t)__cvta_generic_to_shared(smq);

    // ---- ones-tile init for Vh rows 16..23 of each batch ----
    for (int i = tid; i < 4 * 8 * 132; i += 256) {
        int bb = i / (8 * 132);
        int rem = i - bb * (8 * 132);
        int pr = rem / 132;
        int cc = rem - pr * 132;
        smq[VH_OFF + bb * 3168 + (16 + pr) * 132 + cc] =
            (pr == 0) ? 0x3C003C00u : 0u;
    }

    // ---- issue A tile (xn, 64 rows x 128 u32, pitch 132) ----
    #pragma unroll
    for (int t = 0; t < 8; t++) {
        int i = tid + t * 256;
        int row = i >> 5, seg = i & 31;
        cp16(sbase + (A_OFF + row * 132 + seg * 4) * 4,
             g_xnh + (size_t)(m0 + row) * 128 + seg * 4);
    }
    asm volatile("cp.async.commit_group;" ::: "memory");

    auto ISSUE_W = [&](int g) {
        int w = g >> 3, c = g & 7, st = g & 1;
        const uint32_t* src = g_wh + (w << 15);
        #pragma unroll
        for (int t = 0; t < 4; t++) {
            int i = tid + t * 256;
            int row = i >> 2, seg = i & 3;
            cp16(sbase + (W_OFF + st * WSTG + row * 20 + seg * 4) * 4,
                 src + (size_t)row * 128 + c * 16 + seg * 4);
        }
        asm volatile("cp.async.commit_group;" ::: "memory");
    };

    const int wm = wid >> 2, wn = wid & 3;   // 2m x 4n warps
    const float* biasp[3] = {bq, bk_, bv};

    float acc[2][8][4];
    #pragma unroll
    for (int tm = 0; tm < 2; tm++)
        #pragma unroll
        for (int nt = 0; nt < 8; nt++)
            #pragma unroll
            for (int i = 0; i < 4; i++) acc[tm][nt][i] = 0.f;

    ISSUE_W(0);

    // ---- gemm phase: 3 weights x 8 chunks of K=32 ----
    #pragma unroll 1
    for (int g = 0; g < 24; g++) {
        if (g < 23) {
            ISSUE_W(g + 1);
            asm volatile("cp.async.wait_group 1;" ::: "memory");
        } else {
            asm volatile("cp.async.wait_group 0;" ::: "memory");
        }
        __syncthreads();
        const int c = g & 7, st = g & 1;
        const uint32_t* A0 = smq + A_OFF + (wm * 32) * 132;
        const uint32_t* B0 = smq + W_OFF + st * WSTG + (wn * 64) * 20;
        #pragma unroll
        for (int kk = 0; kk < 2; kk++) {
            uint32_t af[2][4];
            #pragma unroll
            for (int tm = 0; tm < 2; tm++) {
                int r = tm * 16 + g4;
                af[tm][0] = A0[r * 132 + c * 16 + kk * 8 + l4];
                af[tm][1] = A0[(r + 8) * 132 + c * 16 + kk * 8 + l4];
                af[tm][2] = A0[r * 132 + c * 16 + kk * 8 + l4 + 4];
                af[tm][3] = A0[(r + 8) * 132 + c * 16 + kk * 8 + l4 + 4];
            }
            #pragma unroll
            for (int nt = 0; nt < 8; nt++) {
                uint32_t fb0 = B0[(nt * 8 + g4) * 20 + kk * 8 + l4];
                uint32_t fb1 = B0[(nt * 8 + g4) * 20 + kk * 8 + l4 + 4];
                #pragma unroll
                for (int tm = 0; tm < 2; tm++)
                    MMA_FP16(acc[tm][nt], af[tm][0], af[tm][1],
                             af[tm][2], af[tm][3], fb0, fb1);
            }
        }
        __syncthreads();

        if (c == 7) {
            // ---- epilogue for weight w: store into attn smem layouts ----
            int w = g >> 3;
            const float* bias = biasp[w];
            if (w < 2) {
                // Q/K: transposed half stores: dst[(b*256+e)*24 + p]
                __half* dst = (__half*)(smq + (w == 0 ? QT_OFF : KT_OFF));
                float bs = (w == 0) ? QPRE : 1.f;
                #pragma unroll
                for (int tm = 0; tm < 2; tm++) {
                    int r0 = wm * 32 + tm * 16 + g4;
                    int b0 = r0 >> 4, p0 = r0 & 15;
                    int p1 = p0 + 8;
                    #pragma unroll
                    for (int nt = 0; nt < 8; nt++) {
                        int e0 = wn * 64 + nt * 8 + l4 * 2;
                        float bx = bias[e0] * bs, by = bias[e0 + 1] * bs;
                        dst[(b0 * 256 + e0) * 24 + p0] =
                            __float2half(acc[tm][nt][0] + bx);
                        dst[(b0 * 256 + e0 + 1) * 24 + p0] =
                            __float2half(acc[tm][nt][1] + by);
                        dst[(b0 * 256 + e0) * 24 + p1] =
                            __float2half(acc[tm][nt][2] + bx);
                        dst[(b0 * 256 + e0 + 1) * 24 + p1] =
                            __float2half(acc[tm][nt][3] + by);
                    }
                }
            } else {
                // V: natural layout Vh[b][p][f-pair]
                #pragma unroll
                for (int tm = 0; tm < 2; tm++) {
                    int r0 = wm * 32 + tm * 16 + g4;
                    int b0 = r0 >> 4, p0 = r0 & 15;
                    int p1 = p0 + 8;
                    #pragma unroll
                    for (int nt = 0; nt < 8; nt++) {
                        int e0 = wn * 64 + nt * 8 + l4 * 2;
                        float bx = bias[e0], by = bias[e0 + 1];
                        smq[VH_OFF + b0 * 3168 + p0 * 132 + (e0 >> 1)] =
                            hpack(acc[tm][nt][0] + bx, acc[tm][nt][1] + by);
                        smq[VH_OFF + b0 * 3168 + p1 * 132 + (e0 >> 1)] =
                            hpack(acc[tm][nt][2] + bx, acc[tm][nt][3] + by);
                    }
                }
            }
            #pragma unroll
            for (int tm = 0; tm < 2; tm++)
                #pragma unroll
                for (int nt = 0; nt < 8; nt++)
                    #pragma unroll
                    for (int i = 0; i < 4; i++) acc[tm][nt][i] = 0.f;
        }
    }
    __syncthreads();

    // ---- attention phase: warp -> (batch = wid>>1, e-half = wid&1) ----
    const int bb = wid >> 1;
    const int eh = wid & 1;
    const int b_glob = blockIdx.x * 4 + bb;
    const uint32_t* QtU = smq + QT_OFF + bb * 3072;
    const uint32_t* KtU = smq + KT_OFF + bb * 3072;
    const uint32_t* VhU = smq + VH_OFF + bb * 3168;

    #pragma unroll 1
    for (int pass = 0; pass < 4; pass++) {
        int e_loc = eh * 128 + pass * 32;

        uint32_t af[2][4];
        #pragma unroll
        for (int tm = 0; tm < 2; tm++) {
            int eb = e_loc + tm * 16;
            af[tm][0] = QtU[(eb + g4) * 12 + l4];
            af[tm][1] = QtU[(eb + g4 + 8) * 12 + l4];
            af[tm][2] = QtU[(eb + g4) * 12 + l4 + 4];
            af[tm][3] = QtU[(eb + g4 + 8) * 12 + l4 + 4];
        }

        float av[2][3][4];
        #pragma unroll
        for (int tm = 0; tm < 2; tm++)
            #pragma unroll
            for (int np = 0; np < 3; np++)
                #pragma unroll
                for (int i = 0; i < 4; i++) av[tm][np][i] = 0.f;

        #pragma unroll 2
        for (int fc = 0; fc < 256; fc += 32) {
            float E[2][4][4];
            #pragma unroll
            for (int nt = 0; nt < 4; nt++) {
                int f = fc + nt * 8 + g4;
                uint32_t kb0 = KtU[f * 12 + l4];
                uint32_t kb1 = KtU[f * 12 + l4 + 4];
                #pragma unroll
                for (int tm = 0; tm < 2; tm++) {
                    float* c = E[tm][nt];
                    c[0] = c[1] = c[2] = c[3] = 0.f;
                    MMA_FP16(c, af[tm][0], af[tm][1], af[tm][2], af[tm][3],
                             kb0, kb1);
                }
            }
            uint32_t Ppk[2][4][2];
            #pragma unroll
            for (int tm = 0; tm < 2; tm++)
                #pragma unroll
                for (int nt = 0; nt < 4; nt++) {
                    float* c = E[tm][nt];
                    Ppk[tm][nt][0] = hex2(hpack(c[0], c[1]));
                    Ppk[tm][nt][1] = hex2(hpack(c[2], c[3]));
                }
            #pragma unroll
            for (int s = 0; s < 2; s++) {
                uint32_t vb0[3], vb1[3];
                #pragma unroll
                for (int np = 0; np < 3; np++) {
                    const uint32_t* vr = VhU + (np * 8 + g4) * 132
                                         + (fc >> 1) + s * 8;
                    vb0[np] = vr[l4];
                    vb1[np] = vr[l4 + 4];
                }
                #pragma unroll
                for (int tm = 0; tm < 2; tm++) {
                    uint32_t a0 = Ppk[tm][2 * s][0];
                    uint32_t a1 = Ppk[tm][2 * s][1];
                    uint32_t a2 = Ppk[tm][2 * s + 1][0];
                    uint32_t a3 = Ppk[tm][2 * s + 1][1];
                    #pragma unroll
                    for (int np = 0; np < 3; np++)
                        MMA_FP16(av[tm][np], a0, a1, a2, a3,
                                 vb0[np], vb1[np]);
                }
            }
        }

        // ---- epilogue: row sums in av[tm][2][0]/[2] on l4==0 lanes ----
        #pragma unroll
        for (int tm = 0; tm < 2; tm++) {
            int src = (lane >> 2) << 2;
            float s0 = __shfl_sync(0xffffffffu, av[tm][2][0], src);
            float s1 = __shfl_sync(0xffffffffu, av[tm][2][2], src);
            float inv0 = 1.f / s0, inv1 = 1.f / s1;
            int e_lo = e_loc + tm * 16 + g4;
            #pragma unroll
            for (int np = 0; np < 2; np++) {
                int p = np * 8 + l4 * 2;
                size_t lo = (size_t)b_glob * FEAT + e_lo * 16 + p;
                size_t hi = lo + 8 * 16;
                float2 x0 = *(const float2*)(x + lo);
                float2 x1 = *(const float2*)(x + hi);
                *(float2*)(out + lo) =
                    make_float2(av[tm][np][0] * inv0 + x0.x,
                                av[tm][np][1] * inv0 + x0.y);
                *(float2*)(out + hi) =
                    make_float2(av[tm][np][2] * inv1 + x1.x,
                                av[tm][np][3] * inv1 + x1.y);
            }
        }
    }
}

// ---------------- launcher ----------------
extern "C" void kernel_launch(void* const* d_in, const int* in_sizes, int n_in,
                              void* d_out, int out_size) {
    const float* x     = (const float*)d_in[0];
    const float* WQ_w  = (const float*)d_in[1];
    const float* WQ_b  = (const float*)d_in[2];
    const float* WK_w  = (const float*)d_in[3];
    const float* WK_b  = (const float*)d_in[4];
    const float* WV_w  = (const float*)d_in[5];
    const float* WV_b  = (const float*)d_in[6];
    const float* gamma = (const float*)d_in[7];
    const float* beta  = (const float*)d_in[8];
    float* out = (float*)d_out;

    cudaFuncSetAttribute(fused_qkv_attn,
                         cudaFuncAttributeMaxDynamicSharedMemorySize,
                         (int)SMEM_FUSED);

    bn_pass1<<<dim3(FEAT / 256, RCHUNKS), 256>>>(x);
    w_fp16<<<384, 256>>>(WQ_w, WK_w, WV_w);
    bn_pass2<<<FEAT / 256, 256>>>(gamma, beta);
    xn_fp16<<<(MROWS * 256 / 8) / 256, 256>>>(x);
    fused_qkv_attn<<<1024, 256, SMEM_FUSED>>>(x, WQ_b, WK_b, WV_b, out);
}